// round 12
// baseline (speedup 1.0000x reference)
#include <cuda_runtime.h>
#include <cstdint>

#define MAXN 50000
#define MAXE 600064
#define F 128
#define LN_EPS 1e-5f

// ---------------- scratch (device globals; no allocation allowed) ----------
__device__ int   g_src[MAXE];
__device__ int   g_dst[MAXE];
__device__ float g_dinv[MAXN];
__device__ int   g_degi[MAXN];
__device__ int   g_off[MAXN + 1];
__device__ int   g_cur[MAXN];
__device__ int2  g_ew[MAXE];      // packed {src, weight bits}
__device__ float g_h[MAXN * F];   // GEMM1 output (read by ALL gather1 chunks)
__device__ float g_h2[MAXN * F];  // gather1 output / GEMM2 input
__device__ float g_h3[MAXN * F];  // GEMM2 output (separate: avoids WAR on g_h)
__device__ int   g_bsum[16];

// -------- convert edges (dtype-probing) + degree count ----------------------
__global__ void k_convert_count(const void* __restrict__ ei_raw, int N, int E) {
    __shared__ int s_is64;
    if (threadIdx.x == 0) {
        const unsigned long long* p = (const unsigned long long*)ei_raw;
        unsigned long long mx = 0;
#pragma unroll
        for (int i = 0; i < 32; i++) mx = mx > p[i] ? mx : p[i];
        s_is64 = (mx < (unsigned long long)N);
    }
    __syncthreads();
    int e = blockIdx.x * blockDim.x + threadIdx.x;
    if (e >= E) return;
    int s, d;
    if (s_is64) {
        const long long* p = (const long long*)ei_raw;
        s = (int)p[e]; d = (int)p[E + e];
    } else {
        const int* p = (const int*)ei_raw;
        s = p[e]; d = p[E + e];
    }
    g_src[e] = s;
    g_dst[e] = d;
    atomicAdd(&g_degi[d], 1);
}

// ---------------- scan phase 1: per-block exclusive scan (4096/block) -------
__global__ void __launch_bounds__(1024)
k_scan1(int n) {
    __shared__ int sh[32];
    const int lane = threadIdx.x & 31;
    const int wid  = threadIdx.x >> 5;
    const int i0 = blockIdx.x * 4096 + threadIdx.x * 4;

    int v0 = (i0 + 0 < n) ? g_degi[i0 + 0] : 0;
    int v1 = (i0 + 1 < n) ? g_degi[i0 + 1] : 0;
    int v2 = (i0 + 2 < n) ? g_degi[i0 + 2] : 0;
    int v3 = (i0 + 3 < n) ? g_degi[i0 + 3] : 0;
    int s = v0 + v1 + v2 + v3;

    int x = s;
#pragma unroll
    for (int o = 1; o < 32; o <<= 1) {
        int y = __shfl_up_sync(0xffffffffu, x, o);
        if (lane >= o) x += y;
    }
    if (lane == 31) sh[wid] = x;
    __syncthreads();
    if (wid == 0) {
        int t = sh[lane];
#pragma unroll
        for (int o = 1; o < 32; o <<= 1) {
            int y = __shfl_up_sync(0xffffffffu, t, o);
            if (lane >= o) t += y;
        }
        sh[lane] = t;
    }
    __syncthreads();
    int excl = x - s + ((wid == 0) ? 0 : sh[wid - 1]);

    if (i0 + 0 < n) g_off[i0 + 0] = excl;
    if (i0 + 1 < n) g_off[i0 + 1] = excl + v0;
    if (i0 + 2 < n) g_off[i0 + 2] = excl + v0 + v1;
    if (i0 + 3 < n) g_off[i0 + 3] = excl + v0 + v1 + v2;
    if (threadIdx.x == 1023) g_bsum[blockIdx.x] = excl + s;
}

// ------- scan phase 2 (fused): add block offsets, init cur & dinv ------------
__global__ void k_scan3(int n, int nblk) {
    __shared__ int s_boff;
    int grp = (blockIdx.x * blockDim.x) >> 12;
    if (threadIdx.x == 0) {
        int s = 0;
        for (int b = 0; b < grp; b++) s += g_bsum[b];
        s_boff = s;
    }
    __syncthreads();
    int i = blockIdx.x * blockDim.x + threadIdx.x;
    if (i < n) {
        int val = g_off[i] + s_boff;
        g_off[i] = val;
        g_cur[i] = val;
        g_dinv[i] = rsqrtf((float)g_degi[i] + 1.0f);
    }
    if (blockIdx.x == 0 && threadIdx.x == 0) {
        int s = 0;
        for (int b = 0; b < nblk; b++) s += g_bsum[b];
        g_off[n] = s;
    }
}

__global__ void k_fill(int E) {
    int e = blockIdx.x * blockDim.x + threadIdx.x;
    if (e >= E) return;
    int s = g_src[e];
    int d = g_dst[e];
    int pos = atomicAdd(&g_cur[d], 1);
    float w = g_dinv[s] * g_dinv[d];
    g_ew[pos] = make_int2(s, __float_as_int(w));
}

// ---------------- SGEMM: H[rows,128] = X[rows,128] @ W[128,128] -------------
// FFMA2 path, R5/R8-measured geometry. rowbase allows chunked launches.
#define GST 256

__global__ void __launch_bounds__(256, 2)
k_gemm128(const float* __restrict__ X, const float* __restrict__ W,
          float* __restrict__ H, int rowbase, int N) {
    extern __shared__ float xs[];   // 64 * GST floats = 64KB

    const int row0 = rowbase + blockIdx.x * 64;
    const int c  = threadIdx.x & 31;
    const int rg = threadIdx.x >> 5;

    // stage + duplicate
    for (int i = threadIdx.x; i < 64 * 32; i += 256) {
        int r  = i >> 5;
        int k4 = i & 31;
        float4 v = make_float4(0.f, 0.f, 0.f, 0.f);
        int row = row0 + r;
        if (row < N)
            v = ((const float4*)(X + (size_t)row * F))[k4];
        float* p = &xs[r * GST + k4 * 8];
        *(float4*)(p)     = make_float4(v.x, v.x, v.y, v.y);
        *(float4*)(p + 4) = make_float4(v.z, v.z, v.w, v.w);
    }
    __syncthreads();

    unsigned long long acc[8][2];
#pragma unroll
    for (int r = 0; r < 8; r++) { acc[r][0] = 0ULL; acc[r][1] = 0ULL; }

    const float* Wc = W + 4 * c;
    const float* xbase = &xs[(rg * 8) * GST];

#pragma unroll 8
    for (int k = 0; k < 128; k++) {
        ulonglong2 w2 = *(const ulonglong2*)(Wc + k * F);
#pragma unroll
        for (int r = 0; r < 8; r++) {
            unsigned long long xd =
                *(const unsigned long long*)(xbase + r * GST + 2 * k);
            asm("fma.rn.f32x2 %0, %1, %2, %0;" : "+l"(acc[r][0]) : "l"(xd), "l"(w2.x));
            asm("fma.rn.f32x2 %0, %1, %2, %0;" : "+l"(acc[r][1]) : "l"(xd), "l"(w2.y));
        }
    }

#pragma unroll
    for (int r = 0; r < 8; r++) {
        int row = row0 + rg * 8 + r;
        if (row < N) {
            float o0, o1, o2, o3;
            asm("mov.b64 {%0, %1}, %2;" : "=f"(o0), "=f"(o1) : "l"(acc[r][0]));
            asm("mov.b64 {%0, %1}, %2;" : "=f"(o2), "=f"(o3) : "l"(acc[r][1]));
            ((float4*)(H + (size_t)row * F))[c] = make_float4(o0, o1, o2, o3);
        }
    }
}

// ------- fused gather + self-loop + bias + LayerNorm + ReLU -----------------
// processes nodes [n0, n1); one warp per node
__global__ void __launch_bounds__(256)
k_gather_ln(const float* __restrict__ h,
            const float* __restrict__ b, const float* __restrict__ g,
            const float* __restrict__ be, float* __restrict__ out,
            int n0, int n1) {
    int warp = n0 + ((blockIdx.x * blockDim.x + threadIdx.x) >> 5);
    int lane = threadIdx.x & 31;
    if (warp >= n1) return;

    const int beg = g_off[warp];
    const int end = g_off[warp + 1];

    float4 acc = make_float4(0.f, 0.f, 0.f, 0.f);

    int e = beg;
    int2 ew_next = make_int2(0, 0);
    if (e < end) ew_next = g_ew[e];
    while (e < end) {
        int   s  = ew_next.x;
        float we = __int_as_float(ew_next.y);
        int en = e + 1;
        if (en < end) ew_next = g_ew[en];
        float4 hv = ((const float4*)(h + (size_t)s * F))[lane];
        acc.x += hv.x * we;
        acc.y += hv.y * we;
        acc.z += hv.z * we;
        acc.w += hv.w * we;
        e = en;
    }

    // self-loop + bias
    float di = g_dinv[warp];
    float sn = di * di;
    float4 hs = ((const float4*)(h + (size_t)warp * F))[lane];
    float4 bv = ((const float4*)b)[lane];
    acc.x += hs.x * sn + bv.x;
    acc.y += hs.y * sn + bv.y;
    acc.z += hs.z * sn + bv.z;
    acc.w += hs.w * sn + bv.w;

    // LayerNorm
    float ssum = acc.x + acc.y + acc.z + acc.w;
#pragma unroll
    for (int o = 16; o; o >>= 1) ssum += __shfl_xor_sync(0xffffffffu, ssum, o);
    float mu = ssum * (1.0f / F);

    float4 dv;
    dv.x = acc.x - mu; dv.y = acc.y - mu; dv.z = acc.z - mu; dv.w = acc.w - mu;
    float ss = dv.x * dv.x + dv.y * dv.y + dv.z * dv.z + dv.w * dv.w;
#pragma unroll
    for (int o = 16; o; o >>= 1) ss += __shfl_xor_sync(0xffffffffu, ss, o);
    float rs = rsqrtf(ss * (1.0f / F) + LN_EPS);

    float4 gv  = ((const float4*)g)[lane];
    float4 bev = ((const float4*)be)[lane];
    float4 o4;
    o4.x = fmaxf(dv.x * rs * gv.x + bev.x, 0.f);
    o4.y = fmaxf(dv.y * rs * gv.y + bev.y, 0.f);
    o4.z = fmaxf(dv.z * rs * gv.z + bev.z, 0.f);
    o4.w = fmaxf(dv.w * rs * gv.w + bev.w, 0.f);
    ((float4*)(out + (size_t)warp * F))[lane] = o4;
}

// ---------------- launch ----------------------------------------------------
extern "C" void kernel_launch(void* const* d_in, const int* in_sizes, int n_in,
                              void* d_out, int out_size) {
    const float* x   = (const float*)d_in[0];
    const void*  ei  = d_in[1];
    const float* W1  = (const float*)d_in[2];
    const float* b1  = (const float*)d_in[3];
    const float* g1  = (const float*)d_in[4];
    const float* be1 = (const float*)d_in[5];
    const float* W2  = (const float*)d_in[6];
    const float* b2  = (const float*)d_in[7];
    const float* g2  = (const float*)d_in[8];
    const float* be2 = (const float*)d_in[9];
    float* out = (float*)d_out;

    const int N = in_sizes[0] / F;
    const int E = in_sizes[1] / 2;

    float *h, *h2, *h3;
    int   *degi;
    cudaGetSymbolAddress((void**)&h,    g_h);
    cudaGetSymbolAddress((void**)&h2,   g_h2);
    cudaGetSymbolAddress((void**)&h3,   g_h3);
    cudaGetSymbolAddress((void**)&degi, g_degi);

    const int GEMM_SMEM = 64 * GST * (int)sizeof(float);
    cudaFuncSetAttribute(k_gemm128,
                         cudaFuncAttributeMaxDynamicSharedMemorySize, GEMM_SMEM);

    const int nbN = (N + 255) / 256;
    const int nbE = (E + 255) / 256;
    const int nbG = (N + 63) / 64;
    const int nbW = (N * 32 + 255) / 256;
    const int nbS = (N + 4095) / 4096;

    // layer-1 pipeline chunking: 4 node chunks, 64-aligned
    const int NCH = 4;
    const int csz = (((N + NCH - 1) / NCH + 63) / 64) * 64;

    cudaStream_t s2;
    cudaEvent_t ev_fork, ev_g1, ev_ch[NCH];
    cudaStreamCreateWithFlags(&s2, cudaStreamNonBlocking);
    cudaEventCreateWithFlags(&ev_fork, cudaEventDisableTiming);
    cudaEventCreateWithFlags(&ev_g1,   cudaEventDisableTiming);
    for (int i = 0; i < NCH; i++)
        cudaEventCreateWithFlags(&ev_ch[i], cudaEventDisableTiming);

    // ---- fork: CSR build on s2, concurrent with layer-1 GEMM on stream 0 ----
    cudaEventRecord(ev_fork, 0);
    cudaStreamWaitEvent(s2, ev_fork, 0);

    cudaMemsetAsync(degi, 0, (size_t)N * sizeof(int), s2);
    k_convert_count<<<nbE, 256, 0, s2>>>(ei, N, E);
    k_scan1<<<nbS, 1024, 0, s2>>>(N);
    k_scan3<<<nbN, 256, 0, s2>>>(N, nbS);
    k_fill<<<nbE, 256, 0, s2>>>(E);

    k_gemm128<<<nbG, 256, GEMM_SMEM>>>(x, W1, h, 0, N);   // stream 0
    cudaEventRecord(ev_g1, 0);
    cudaStreamWaitEvent(s2, ev_g1, 0);                     // s2 now has CSR + GEMM1

    // ---- layer-1 gather in chunks on s2; GEMM2 chunks on s0 chase them ----
    // gather1 reads ALL of g_h; GEMM2 writes g_h3 (disjoint) -> no WAR hazard.
    for (int i = 0; i < NCH; i++) {
        int a = i * csz;
        int bnd = (i == NCH - 1) ? N : (a + csz);
        if (a >= N) { cudaEventRecord(ev_ch[i], s2); continue; }
        int nodes = bnd - a;
        int blks  = (nodes * 32 + 255) / 256;
        k_gather_ln<<<blks, 256, 0, s2>>>(h, b1, g1, be1, h2, a, bnd);
        cudaEventRecord(ev_ch[i], s2);
    }
    for (int i = 0; i < NCH; i++) {
        int a = i * csz;
        int bnd = (i == NCH - 1) ? N : (a + csz);
        if (a >= N) continue;
        cudaStreamWaitEvent(0, ev_ch[i], 0);
        int rows = bnd - a;
        int blks = (rows + 63) / 64;
        k_gemm128<<<blks, 256, GEMM_SMEM>>>(h2, W2, h3, a, N);
    }

    // ---- final gather (needs all GEMM2 rows; not chunkable) ----
    k_gather_ln<<<nbW, 256>>>(h3, b2, g2, be2, out, 0, N);
}

// round 13
// speedup vs baseline: 1.1274x; 1.1274x over previous
#include <cuda_runtime.h>
#include <cstdint>

#define MAXN 50000
#define MAXE 600064
#define F 128
#define LN_EPS 1e-5f

// ---------------- scratch (device globals; no allocation allowed) ----------
__device__ int   g_src[MAXE];
__device__ int   g_dst[MAXE];
__device__ float g_dinv[MAXN];
__device__ int   g_degi[MAXN];
__device__ int   g_off[MAXN + 1];
__device__ int   g_cur[MAXN];
__device__ int2  g_ew[MAXE];      // packed {src, weight bits}
__device__ float g_h[MAXN * F];
__device__ float g_h2[MAXN * F];
__device__ int   g_bsum[16];

// -------- convert edges (dtype-probing) + degree count ----------------------
__global__ void k_convert_count(const void* __restrict__ ei_raw, int N, int E) {
    __shared__ int s_is64;
    if (threadIdx.x == 0) {
        const unsigned long long* p = (const unsigned long long*)ei_raw;
        unsigned long long mx = 0;
#pragma unroll
        for (int i = 0; i < 32; i++) mx = mx > p[i] ? mx : p[i];
        s_is64 = (mx < (unsigned long long)N);
    }
    __syncthreads();
    int e = blockIdx.x * blockDim.x + threadIdx.x;
    if (e >= E) return;
    int s, d;
    if (s_is64) {
        const long long* p = (const long long*)ei_raw;
        s = (int)p[e]; d = (int)p[E + e];
    } else {
        const int* p = (const int*)ei_raw;
        s = p[e]; d = p[E + e];
    }
    g_src[e] = s;
    g_dst[e] = d;
    atomicAdd(&g_degi[d], 1);
}

// ---------------- scan phase 1: per-block exclusive scan (4096/block) -------
__global__ void __launch_bounds__(1024)
k_scan1(int n) {
    __shared__ int sh[32];
    const int lane = threadIdx.x & 31;
    const int wid  = threadIdx.x >> 5;
    const int i0 = blockIdx.x * 4096 + threadIdx.x * 4;

    int v0 = (i0 + 0 < n) ? g_degi[i0 + 0] : 0;
    int v1 = (i0 + 1 < n) ? g_degi[i0 + 1] : 0;
    int v2 = (i0 + 2 < n) ? g_degi[i0 + 2] : 0;
    int v3 = (i0 + 3 < n) ? g_degi[i0 + 3] : 0;
    int s = v0 + v1 + v2 + v3;

    int x = s;
#pragma unroll
    for (int o = 1; o < 32; o <<= 1) {
        int y = __shfl_up_sync(0xffffffffu, x, o);
        if (lane >= o) x += y;
    }
    if (lane == 31) sh[wid] = x;
    __syncthreads();
    if (wid == 0) {
        int t = sh[lane];
#pragma unroll
        for (int o = 1; o < 32; o <<= 1) {
            int y = __shfl_up_sync(0xffffffffu, t, o);
            if (lane >= o) t += y;
        }
        sh[lane] = t;
    }
    __syncthreads();
    int excl = x - s + ((wid == 0) ? 0 : sh[wid - 1]);

    if (i0 + 0 < n) g_off[i0 + 0] = excl;
    if (i0 + 1 < n) g_off[i0 + 1] = excl + v0;
    if (i0 + 2 < n) g_off[i0 + 2] = excl + v0 + v1;
    if (i0 + 3 < n) g_off[i0 + 3] = excl + v0 + v1 + v2;
    if (threadIdx.x == 1023) g_bsum[blockIdx.x] = excl + s;
}

// ------- scan phase 2 (fused): add block offsets, init cur & dinv ------------
__global__ void k_scan3(int n, int nblk) {
    __shared__ int s_boff;
    int grp = (blockIdx.x * blockDim.x) >> 12;
    if (threadIdx.x == 0) {
        int s = 0;
        for (int b = 0; b < grp; b++) s += g_bsum[b];
        s_boff = s;
    }
    __syncthreads();
    int i = blockIdx.x * blockDim.x + threadIdx.x;
    if (i < n) {
        int val = g_off[i] + s_boff;
        g_off[i] = val;
        g_cur[i] = val;
        g_dinv[i] = rsqrtf((float)g_degi[i] + 1.0f);
    }
    if (blockIdx.x == 0 && threadIdx.x == 0) {
        int s = 0;
        for (int b = 0; b < nblk; b++) s += g_bsum[b];
        g_off[n] = s;
    }
}

__global__ void k_fill(int E) {
    int e = blockIdx.x * blockDim.x + threadIdx.x;
    if (e >= E) return;
    int s = g_src[e];
    int d = g_dst[e];
    int pos = atomicAdd(&g_cur[d], 1);
    float w = g_dinv[s] * g_dinv[d];
    g_ew[pos] = make_int2(s, __float_as_int(w));
}

// ---------------- SGEMM: H[N,128] = X[N,128] @ W[128,128] ------------------
// FFMA2 path, R5/R8-measured geometry (8 rows x 4 cols per thread).
#define GST 256

__global__ void __launch_bounds__(256, 2)
k_gemm128(const float* __restrict__ X, const float* __restrict__ W,
          float* __restrict__ H, int N) {
    extern __shared__ float xs[];   // 64 * GST floats = 64KB

    const int row0 = blockIdx.x * 64;
    const int c  = threadIdx.x & 31;
    const int rg = threadIdx.x >> 5;

    // stage + duplicate
    for (int i = threadIdx.x; i < 64 * 32; i += 256) {
        int r  = i >> 5;
        int k4 = i & 31;
        float4 v = make_float4(0.f, 0.f, 0.f, 0.f);
        int row = row0 + r;
        if (row < N)
            v = ((const float4*)(X + (size_t)row * F))[k4];
        float* p = &xs[r * GST + k4 * 8];
        *(float4*)(p)     = make_float4(v.x, v.x, v.y, v.y);
        *(float4*)(p + 4) = make_float4(v.z, v.z, v.w, v.w);
    }
    __syncthreads();

    unsigned long long acc[8][2];
#pragma unroll
    for (int r = 0; r < 8; r++) { acc[r][0] = 0ULL; acc[r][1] = 0ULL; }

    const float* Wc = W + 4 * c;
    const float* xbase = &xs[(rg * 8) * GST];

#pragma unroll 8
    for (int k = 0; k < 128; k++) {
        ulonglong2 w2 = *(const ulonglong2*)(Wc + k * F);
#pragma unroll
        for (int r = 0; r < 8; r++) {
            unsigned long long xd =
                *(const unsigned long long*)(xbase + r * GST + 2 * k);
            asm("fma.rn.f32x2 %0, %1, %2, %0;" : "+l"(acc[r][0]) : "l"(xd), "l"(w2.x));
            asm("fma.rn.f32x2 %0, %1, %2, %0;" : "+l"(acc[r][1]) : "l"(xd), "l"(w2.y));
        }
    }

#pragma unroll
    for (int r = 0; r < 8; r++) {
        int row = row0 + rg * 8 + r;
        if (row < N) {
            float o0, o1, o2, o3;
            asm("mov.b64 {%0, %1}, %2;" : "=f"(o0), "=f"(o1) : "l"(acc[r][0]));
            asm("mov.b64 {%0, %1}, %2;" : "=f"(o2), "=f"(o3) : "l"(acc[r][1]));
            ((float4*)(H + (size_t)row * F))[c] = make_float4(o0, o1, o2, o3);
        }
    }
}

// ------- fused gather + self-loop + bias + LayerNorm + ReLU -----------------
// one warp per node; edge loop unrolled x2 so TWO h-row loads are in flight
// per warp (MLP=2) instead of one.
__global__ void __launch_bounds__(256)
k_gather_ln(const float* __restrict__ h,
            const float* __restrict__ b, const float* __restrict__ g,
            const float* __restrict__ be, float* __restrict__ out, int N) {
    int warp = (blockIdx.x * blockDim.x + threadIdx.x) >> 5;
    int lane = threadIdx.x & 31;
    if (warp >= N) return;

    const int beg = g_off[warp];
    const int end = g_off[warp + 1];

    float4 acc = make_float4(0.f, 0.f, 0.f, 0.f);

    int e = beg;
    for (; e + 2 <= end; e += 2) {
        int2 ew0 = g_ew[e];
        int2 ew1 = g_ew[e + 1];
        float4 h0 = ((const float4*)(h + (size_t)ew0.x * F))[lane];
        float4 h1 = ((const float4*)(h + (size_t)ew1.x * F))[lane];
        float w0 = __int_as_float(ew0.y);
        float w1 = __int_as_float(ew1.y);
        acc.x += h0.x * w0; acc.y += h0.y * w0;
        acc.z += h0.z * w0; acc.w += h0.w * w0;
        acc.x += h1.x * w1; acc.y += h1.y * w1;
        acc.z += h1.z * w1; acc.w += h1.w * w1;
    }
    if (e < end) {
        int2 ew0 = g_ew[e];
        float4 h0 = ((const float4*)(h + (size_t)ew0.x * F))[lane];
        float w0 = __int_as_float(ew0.y);
        acc.x += h0.x * w0; acc.y += h0.y * w0;
        acc.z += h0.z * w0; acc.w += h0.w * w0;
    }

    // self-loop + bias
    float di = g_dinv[warp];
    float sn = di * di;
    float4 hs = ((const float4*)(h + (size_t)warp * F))[lane];
    float4 bv = ((const float4*)b)[lane];
    acc.x += hs.x * sn + bv.x;
    acc.y += hs.y * sn + bv.y;
    acc.z += hs.z * sn + bv.z;
    acc.w += hs.w * sn + bv.w;

    // LayerNorm
    float ssum = acc.x + acc.y + acc.z + acc.w;
#pragma unroll
    for (int o = 16; o; o >>= 1) ssum += __shfl_xor_sync(0xffffffffu, ssum, o);
    float mu = ssum * (1.0f / F);

    float4 dv;
    dv.x = acc.x - mu; dv.y = acc.y - mu; dv.z = acc.z - mu; dv.w = acc.w - mu;
    float ss = dv.x * dv.x + dv.y * dv.y + dv.z * dv.z + dv.w * dv.w;
#pragma unroll
    for (int o = 16; o; o >>= 1) ss += __shfl_xor_sync(0xffffffffu, ss, o);
    float rs = rsqrtf(ss * (1.0f / F) + LN_EPS);

    float4 gv  = ((const float4*)g)[lane];
    float4 bev = ((const float4*)be)[lane];
    float4 o4;
    o4.x = fmaxf(dv.x * rs * gv.x + bev.x, 0.f);
    o4.y = fmaxf(dv.y * rs * gv.y + bev.y, 0.f);
    o4.z = fmaxf(dv.z * rs * gv.z + bev.z, 0.f);
    o4.w = fmaxf(dv.w * rs * gv.w + bev.w, 0.f);
    ((float4*)(out + (size_t)warp * F))[lane] = o4;
}

// ---------------- launch ----------------------------------------------------
extern "C" void kernel_launch(void* const* d_in, const int* in_sizes, int n_in,
                              void* d_out, int out_size) {
    const float* x   = (const float*)d_in[0];
    const void*  ei  = d_in[1];
    const float* W1  = (const float*)d_in[2];
    const float* b1  = (const float*)d_in[3];
    const float* g1  = (const float*)d_in[4];
    const float* be1 = (const float*)d_in[5];
    const float* W2  = (const float*)d_in[6];
    const float* b2  = (const float*)d_in[7];
    const float* g2  = (const float*)d_in[8];
    const float* be2 = (const float*)d_in[9];
    float* out = (float*)d_out;

    const int N = in_sizes[0] / F;
    const int E = in_sizes[1] / 2;

    float *h, *h2;
    int   *degi;
    cudaGetSymbolAddress((void**)&h,    g_h);
    cudaGetSymbolAddress((void**)&h2,   g_h2);
    cudaGetSymbolAddress((void**)&degi, g_degi);

    const int GEMM_SMEM = 64 * GST * (int)sizeof(float);
    cudaFuncSetAttribute(k_gemm128,
                         cudaFuncAttributeMaxDynamicSharedMemorySize, GEMM_SMEM);

    const int nbN = (N + 255) / 256;
    const int nbE = (E + 255) / 256;
    const int nbG = (N + 63) / 64;
    const int nbW = (N * 32 + 255) / 256;
    const int nbS = (N + 4095) / 4096;

    // R10 coarse fork-join schedule (measured best): CSR on s2 || GEMM1 on s0.
    cudaStream_t s2;
    cudaEvent_t ev_fork, ev_join;
    cudaStreamCreateWithFlags(&s2, cudaStreamNonBlocking);
    cudaEventCreateWithFlags(&ev_fork, cudaEventDisableTiming);
    cudaEventCreateWithFlags(&ev_join, cudaEventDisableTiming);

    cudaEventRecord(ev_fork, 0);
    cudaStreamWaitEvent(s2, ev_fork, 0);

    cudaMemsetAsync(degi, 0, (size_t)N * sizeof(int), s2);
    k_convert_count<<<nbE, 256, 0, s2>>>(ei, N, E);
    k_scan1<<<nbS, 1024, 0, s2>>>(N);
    k_scan3<<<nbN, 256, 0, s2>>>(N, nbS);
    k_fill<<<nbE, 256, 0, s2>>>(E);
    cudaEventRecord(ev_join, s2);

    k_gemm128<<<nbG, 256, GEMM_SMEM>>>(x, W1, h, N);   // stream 0

    cudaStreamWaitEvent(0, ev_join, 0);

    k_gather_ln<<<nbW, 256>>>(h, b1, g1, be1, h2, N);

    // ---- layer 2 (serial chain on stream 0) ----
    k_gemm128<<<nbG, 256, GEMM_SMEM>>>(h2, W2, h, N);
    k_gather_ln<<<nbW, 256>>>(h, b2, g2, be2, out, N);
}